// round 1
// baseline (speedup 1.0000x reference)
#include <cuda_runtime.h>
#include <math.h>

#define NBATCH 2
#define SEQL   2048
#define NHEAD  8
#define HDIM   64
#define DMODEL 512
#define CATD   128
#define NHTOT  16   // NBATCH * NHEAD

// Scratch (allocation-free per harness rules): 16MB + 16MB + 8MB
__device__ float g_A[(size_t)NHTOT * SEQL * CATD];  // [nh][l][0:64]=q*cos(pq), [64:128]=q*sin(pq)
__device__ float g_B[(size_t)NHTOT * SEQL * CATD];  // [nh][l][...] = coeff*k*{cos,sin}(pk)
__device__ float g_V[(size_t)NHTOT * SEQL * HDIM];  // [nh][l][dd]

__device__ __forceinline__ float softplus_f(float x) {
    // log(1+exp(x)) = max(x,0) + log1p(exp(-|x|))
    return x > 0.f ? x + log1pf(expf(-x)) : log1pf(expf(x));
}

// Range-reduce angle to [-pi,pi] before sincos so even fast-math intrinsics stay accurate.
__device__ __forceinline__ void sincos_red(float ang, float* s, float* c) {
    const float INV2PI = 0.15915494309189535f;
    const float PI2_HI = 6.28318548202514648f;   // float(2*pi)
    const float PI2_LO = -1.74845553e-7f;        // 2*pi - PI2_HI
    float k = rintf(ang * INV2PI);
    float r = fmaf(-k, PI2_HI, ang);
    r = fmaf(-k, PI2_LO, r);
    sincosf(r, s, c);
}

// ---------------------------------------------------------------------------
// Projection GEMM (NT): out[m][col] = sum_k A[m][k] * W[col][k]
// mode 0: Q path -> g_A (softplus + phase cos/sin)
// mode 1: K path -> g_B (softplus * coeff + phase cos/sin)
// mode 2: V path -> g_V (plain)
// ---------------------------------------------------------------------------
__global__ __launch_bounds__(256) void proj_kernel(
    const float* __restrict__ A, const float* __restrict__ W,
    const float* __restrict__ pw, const float* __restrict__ pb,
    const float* __restrict__ coeff, int mode)
{
    __shared__ float As[64][33];
    __shared__ float Ws[64][33];
    int tid = threadIdx.x;
    int tx = tid & 15, ty = tid >> 4;
    int m0 = blockIdx.x * 64;
    int c0 = blockIdx.y * 64;

    float acc[4][4];
    #pragma unroll
    for (int i = 0; i < 4; ++i)
        #pragma unroll
        for (int j = 0; j < 4; ++j) acc[i][j] = 0.f;

    for (int k0 = 0; k0 < DMODEL; k0 += 32) {
        #pragma unroll
        for (int it = 0; it < 8; ++it) {
            int idx = it * 256 + tid;
            int r = idx >> 5, c = idx & 31;
            As[r][c] = A[(size_t)(m0 + r) * DMODEL + k0 + c];
            Ws[r][c] = W[(size_t)(c0 + r) * DMODEL + k0 + c];
        }
        __syncthreads();
        #pragma unroll
        for (int kk = 0; kk < 32; ++kk) {
            float a[4], b[4];
            #pragma unroll
            for (int i = 0; i < 4; ++i) a[i] = As[ty * 4 + i][kk];
            #pragma unroll
            for (int j = 0; j < 4; ++j) b[j] = Ws[tx * 4 + j][kk];
            #pragma unroll
            for (int i = 0; i < 4; ++i)
                #pragma unroll
                for (int j = 0; j < 4; ++j)
                    acc[i][j] = fmaf(a[i], b[j], acc[i][j]);
        }
        __syncthreads();
    }

    #pragma unroll
    for (int i = 0; i < 4; ++i) {
        int m = m0 + ty * 4 + i;
        int n = m >> 11, l = m & (SEQL - 1);
        #pragma unroll
        for (int j = 0; j < 4; ++j) {
            int col = c0 + tx * 4 + j;          // col == h*64+dd, also index into pw/pb/coeff
            int h = col >> 6, dd = col & 63;
            float x = acc[i][j];
            size_t base = (size_t)(n * NHEAD + h) * SEQL + l;
            if (mode == 2) {
                g_V[base * HDIM + dd] = x;
            } else {
                float w = pw[col];
                float sn, cs;
                if (mode == 0) {
                    float sp = softplus_f(x);
                    float ang = (float)l * w + pb[col];
                    sincos_red(ang, &sn, &cs);
                    g_A[base * CATD + dd]      = sp * cs;
                    g_A[base * CATD + 64 + dd] = sp * sn;
                } else {
                    float sp = softplus_f(x) * coeff[col];
                    float ang = (float)l * w;
                    sincos_red(ang, &sn, &cs);
                    g_B[base * CATD + dd]      = sp * cs;
                    g_B[base * CATD + 64 + dd] = sp * sn;
                }
            }
        }
    }
}

// ---------------------------------------------------------------------------
// Causal attention: per (n,h), per 64-row q tile:
//   for each k tile <= q tile: S = A_tile(64x128) . B_tile^T(128x64)  (mask diag)
//   accumulate AV += S.V_tile, abssum += sum_k |S| ; out = AV / abssum
// ---------------------------------------------------------------------------
#define BQ 64
#define BK 64
#define PADK 68      // 68*4 = 272B row pitch, 16B aligned, banks offset by 4
#define APITCH 132

// smem float offsets
#define OFF_A   0          // a_s [64][132]   8448
#define OFF_BT  8448       // bT  [128][68]   8704
#define OFF_V   17152      // v_s [64][68]    4352
#define OFF_S   21504      // s_s [64][68]    4352
#define OFF_ROW 25856      // rows[64]
#define ATTN_SMEM_BYTES (25920 * 4)

__global__ __launch_bounds__(256) void attn_kernel(float* __restrict__ out)
{
    extern __shared__ float sm[];
    float (*a_s)[APITCH] = (float(*)[APITCH])(sm + OFF_A);
    float (*bT)[PADK]    = (float(*)[PADK])(sm + OFF_BT);
    float (*v_s)[PADK]   = (float(*)[PADK])(sm + OFF_V);
    float (*s_s)[PADK]   = (float(*)[PADK])(sm + OFF_S);
    float* rows          = sm + OFF_ROW;

    int tid = threadIdx.x;
    int tx = tid & 15, ty = tid >> 4;
    int nh = blockIdx.y;
    int n = nh >> 3, h = nh & 7;
    // heavy tiles (large qt) first for better tail balance
    int qt = (int)gridDim.x - 1 - (int)blockIdx.x;
    int q0g = qt * BQ;

    const float* Ab = g_A + (size_t)nh * SEQL * CATD;
    const float* Bb = g_B + (size_t)nh * SEQL * CATD;
    const float* Vb = g_V + (size_t)nh * SEQL * HDIM;

    // load A tile once (reused for all k tiles)
    #pragma unroll
    for (int it = 0; it < 32; ++it) {
        int idx = it * 256 + tid;
        int r = idx >> 7, c = idx & 127;
        a_s[r][c] = Ab[(size_t)(q0g + r) * CATD + c];
    }

    float av[4][4];
    #pragma unroll
    for (int i = 0; i < 4; ++i)
        #pragma unroll
        for (int j = 0; j < 4; ++j) av[i][j] = 0.f;
    float asum[4] = {0.f, 0.f, 0.f, 0.f};

    for (int kt = 0; kt <= qt; ++kt) {
        int k0g = kt * BK;
        __syncthreads();   // prior stage-2 done before overwriting bT/v_s (also covers a_s on iter 0)
        #pragma unroll
        for (int it = 0; it < 32; ++it) {
            int idx = it * 256 + tid;
            int r = idx >> 7, c = idx & 127;
            bT[c][r] = Bb[(size_t)(k0g + r) * CATD + c];   // transpose on store
        }
        #pragma unroll
        for (int it = 0; it < 16; ++it) {
            int idx = it * 256 + tid;
            int r = idx >> 6, c = idx & 63;
            v_s[r][c] = Vb[(size_t)(k0g + r) * HDIM + c];
        }
        __syncthreads();

        // stage 1: 64x64 score tile, K=128
        float s[4][4];
        #pragma unroll
        for (int i = 0; i < 4; ++i)
            #pragma unroll
            for (int j = 0; j < 4; ++j) s[i][j] = 0.f;

        #pragma unroll 4
        for (int kk = 0; kk < CATD; ++kk) {
            float4 b4 = *(const float4*)&bT[kk][tx * 4];
            float a[4];
            #pragma unroll
            for (int i = 0; i < 4; ++i) a[i] = a_s[ty * 4 + i][kk];
            #pragma unroll
            for (int i = 0; i < 4; ++i) {
                s[i][0] = fmaf(a[i], b4.x, s[i][0]);
                s[i][1] = fmaf(a[i], b4.y, s[i][1]);
                s[i][2] = fmaf(a[i], b4.z, s[i][2]);
                s[i][3] = fmaf(a[i], b4.w, s[i][3]);
            }
        }

        // mask (diagonal tile only) + stage score tile to smem
        bool diag = (kt == qt);
        #pragma unroll
        for (int i = 0; i < 4; ++i) {
            int qg = q0g + ty * 4 + i;
            #pragma unroll
            for (int j = 0; j < 4; ++j) {
                float val = s[i][j];
                if (diag && (k0g + tx * 4 + j > qg)) val = 0.f;
                s_s[ty * 4 + i][tx * 4 + j] = val;
            }
        }
        __syncthreads();

        // stage 2: AV accumulation + row abs-sum
        #pragma unroll 4
        for (int k = 0; k < BK; ++k) {
            float4 v4 = *(const float4*)&v_s[k][tx * 4];
            float sf[4];
            #pragma unroll
            for (int i = 0; i < 4; ++i) sf[i] = s_s[ty * 4 + i][k];
            #pragma unroll
            for (int i = 0; i < 4; ++i) {
                av[i][0] = fmaf(sf[i], v4.x, av[i][0]);
                av[i][1] = fmaf(sf[i], v4.y, av[i][1]);
                av[i][2] = fmaf(sf[i], v4.z, av[i][2]);
                av[i][3] = fmaf(sf[i], v4.w, av[i][3]);
            }
            if (tx == 0) {
                #pragma unroll
                for (int i = 0; i < 4; ++i) asum[i] += fabsf(sf[i]);
            }
        }
    }

    __syncthreads();
    if (tx == 0) {
        #pragma unroll
        for (int i = 0; i < 4; ++i) rows[ty * 4 + i] = asum[i];
    }
    __syncthreads();

    #pragma unroll
    for (int i = 0; i < 4; ++i) {
        int ql = ty * 4 + i;
        float inv = 1.0f / rows[ql];
        int l = q0g + ql;
        float* o = out + ((size_t)(n * SEQL + l)) * DMODEL + h * HDIM + tx * 4;
        #pragma unroll
        for (int j = 0; j < 4; ++j) o[j] = av[i][j] * inv;
    }
}

extern "C" void kernel_launch(void* const* d_in, const int* in_sizes, int n_in,
                              void* d_out, int out_size)
{
    const float* query = (const float*)d_in[0];
    const float* key   = (const float*)d_in[1];
    const float* Wq    = (const float*)d_in[2];
    const float* Wk    = (const float*)d_in[3];
    const float* Wv    = (const float*)d_in[4];
    const float* coeff = (const float*)d_in[5];
    const float* pw    = (const float*)d_in[6];
    const float* pb    = (const float*)d_in[7];
    float* out = (float*)d_out;

    dim3 pgrid(64, 8);           // 4096/64 x 512/64
    proj_kernel<<<pgrid, 256>>>(query, Wq, pw, pb, coeff, 0);
    proj_kernel<<<pgrid, 256>>>(key,   Wk, pw, pb, coeff, 1);
    proj_kernel<<<pgrid, 256>>>(key,   Wv, pw, pb, coeff, 2);

    cudaFuncSetAttribute(attn_kernel,
                         cudaFuncAttributeMaxDynamicSharedMemorySize,
                         ATTN_SMEM_BYTES);
    attn_kernel<<<dim3(SEQL / BQ, NHTOT), 256, ATTN_SMEM_BYTES>>>(out);
}

// round 4
// speedup vs baseline: 2.9474x; 2.9474x over previous
#include <cuda_runtime.h>
#include <math.h>
#include <cstdint>

#define SEQL   2048
#define NHEAD  8
#define DMODEL 512
#define HDIM   64
#define CATD   128
#define NHTOT  16

// Scratch (allocation-free). Values stored pre-rounded to tf32 bit patterns.
__device__ float g_A [(size_t)NHTOT * SEQL * CATD];   // [nh][l][c]   A operand (K-major)
__device__ float g_B [(size_t)NHTOT * SEQL * CATD];   // [nh][l][c]   B operand (K-major)
__device__ float g_Vt[(size_t)NHTOT * HDIM * SEQL];   // [nh][d][l]   stage-2 B operand (K-major)

#define DINL __device__ __forceinline__

DINL uint32_t f2tf(float f) {           // round fp32 -> tf32 (rna), fp32 bit layout
    uint32_t u;
    asm("cvt.rna.tf32.f32 %0, %1;" : "=r"(u) : "f"(f));
    return u;
}

// m16n8k8 tf32 MMA, fp32 accumulate (legacy mma.sync path, base sm_103 ISA)
DINL void mma8(float* d, const uint32_t* a, const uint32_t* b) {
    asm volatile("mma.sync.aligned.m16n8k8.row.col.f32.tf32.tf32.f32 "
        "{%0,%1,%2,%3}, {%4,%5,%6,%7}, {%8,%9}, {%0,%1,%2,%3};"
        : "+f"(d[0]), "+f"(d[1]), "+f"(d[2]), "+f"(d[3])
        : "r"(a[0]), "r"(a[1]), "r"(a[2]), "r"(a[3]), "r"(b[0]), "r"(b[1]));
}

DINL float softplus_f(float x) {
    return fmaxf(x, 0.f) + log1pf(__expf(-fabsf(x)));
}
DINL void sincos_red(float ang, float* s, float* c) {
    const float INV2PI = 0.15915494309189535f;
    const float PI2_HI = 6.28318548202514648f;
    const float PI2_LO = -1.74845553e-7f;
    float k = rintf(ang * INV2PI);
    float r = fmaf(-k, PI2_HI, ang);
    r = fmaf(-k, PI2_LO, r);
    *s = __sinf(r);
    *c = __cosf(r);
}

// ─────────────────────────── Projection GEMM (tf32 mma.sync) ────────────────
// C(128x128) = X_tile · W_tile^T over K=512.  8 warps: 4(M) x 2(N), warp tile 32x64.
// Epilogue: mode 0 -> g_A (softplus, phase+bias), 1 -> g_B (softplus*coeff, phase), 2 -> g_Vt.
#define PJ_PITCH 132
#define PJ_SMEM  (2 * 128 * PJ_PITCH * 4)

__global__ __launch_bounds__(256) void proj_tc(
    const float* __restrict__ query, const float* __restrict__ key,
    const float* __restrict__ Wq, const float* __restrict__ Wk, const float* __restrict__ Wv,
    const float* __restrict__ coeff, const float* __restrict__ pw, const float* __restrict__ pb)
{
    extern __shared__ float sm[];
    float (*Xs)[PJ_PITCH] = (float(*)[PJ_PITCH])sm;
    float (*Ws)[PJ_PITCH] = (float(*)[PJ_PITCH])(sm + 128 * PJ_PITCH);

    int tid = threadIdx.x, wid = tid >> 5, lane = tid & 31;
    int warpM = wid >> 1, warpN = wid & 1;
    int g = lane >> 2, t = lane & 3;
    int mode = blockIdx.z;
    const float* X = (mode == 0) ? query : key;
    const float* W = (mode == 0) ? Wq : (mode == 1 ? Wk : Wv);
    int m0 = blockIdx.x * 128;
    int c0 = blockIdx.y * 128;

    float acc[2][8][4];
    #pragma unroll
    for (int mb = 0; mb < 2; ++mb)
        #pragma unroll
        for (int nb = 0; nb < 8; ++nb)
            #pragma unroll
            for (int r = 0; r < 4; ++r) acc[mb][nb][r] = 0.f;

    for (int kc = 0; kc < 4; ++kc) {
        __syncthreads();
        #pragma unroll
        for (int it = 0; it < 16; ++it) {
            int idx = it * 256 + tid;
            int r = idx >> 5, c4 = (idx & 31) * 4;
            float4 vx = *(const float4*)(X + (size_t)(m0 + r) * DMODEL + kc * 128 + c4);
            Xs[r][c4 + 0] = __uint_as_float(f2tf(vx.x));
            Xs[r][c4 + 1] = __uint_as_float(f2tf(vx.y));
            Xs[r][c4 + 2] = __uint_as_float(f2tf(vx.z));
            Xs[r][c4 + 3] = __uint_as_float(f2tf(vx.w));
            float4 vw = *(const float4*)(W + (size_t)(c0 + r) * DMODEL + kc * 128 + c4);
            Ws[r][c4 + 0] = __uint_as_float(f2tf(vw.x));
            Ws[r][c4 + 1] = __uint_as_float(f2tf(vw.y));
            Ws[r][c4 + 2] = __uint_as_float(f2tf(vw.z));
            Ws[r][c4 + 3] = __uint_as_float(f2tf(vw.w));
        }
        __syncthreads();

        #pragma unroll 4
        for (int ks = 0; ks < 16; ++ks) {
            int k = ks * 8;
            uint32_t a[2][4];
            #pragma unroll
            for (int mb = 0; mb < 2; ++mb) {
                int r0 = warpM * 32 + mb * 16;
                a[mb][0] = __float_as_uint(Xs[r0 + g][k + t]);
                a[mb][1] = __float_as_uint(Xs[r0 + g + 8][k + t]);
                a[mb][2] = __float_as_uint(Xs[r0 + g][k + t + 4]);
                a[mb][3] = __float_as_uint(Xs[r0 + g + 8][k + t + 4]);
            }
            uint32_t b[8][2];
            #pragma unroll
            for (int nb = 0; nb < 8; ++nb) {
                int n0 = warpN * 64 + nb * 8;
                b[nb][0] = __float_as_uint(Ws[n0 + g][k + t]);
                b[nb][1] = __float_as_uint(Ws[n0 + g][k + t + 4]);
            }
            #pragma unroll
            for (int mb = 0; mb < 2; ++mb)
                #pragma unroll
                for (int nb = 0; nb < 8; ++nb)
                    mma8(acc[mb][nb], a[mb], b[nb]);
        }
    }

    // epilogue
    #pragma unroll
    for (int mb = 0; mb < 2; ++mb) {
        #pragma unroll
        for (int nb = 0; nb < 8; ++nb) {
            #pragma unroll
            for (int r = 0; r < 4; ++r) {
                int row = warpM * 32 + mb * 16 + g + (r >> 1) * 8;
                int col = warpN * 64 + nb * 8 + 2 * t + (r & 1);
                int m = m0 + row;
                int n = m >> 11, l = m & (SEQL - 1);
                int c = c0 + col;
                int h = c >> 6, dd = c & 63;
                float x = acc[mb][nb][r];
                if (mode == 2) {
                    g_Vt[((size_t)((n * NHEAD + h) * HDIM + dd)) * SEQL + l] =
                        __uint_as_float(f2tf(x));
                } else {
                    size_t base = ((size_t)(n * NHEAD + h) * SEQL + l) * CATD;
                    float w = pw[c];
                    float sn, cs;
                    if (mode == 0) {
                        float sp = softplus_f(x);
                        sincos_red((float)l * w + pb[c], &sn, &cs);
                        g_A[base + dd]      = __uint_as_float(f2tf(sp * cs));
                        g_A[base + 64 + dd] = __uint_as_float(f2tf(sp * sn));
                    } else {
                        float sp = softplus_f(x) * coeff[c];
                        sincos_red((float)l * w, &sn, &cs);
                        g_B[base + dd]      = __uint_as_float(f2tf(sp * cs));
                        g_B[base + 64 + dd] = __uint_as_float(f2tf(sp * sn));
                    }
                }
            }
        }
    }
}

// ─────────────────────────── Attention (tf32 mma.sync, causal, abs-norm) ────
// CTA = (nh, 128 q rows). Per 128-key chunk kt<=qt:
//   mma1: S(128x128) = A · B^T   (regs)
//   epilogue: causal mask, asum += Σ|S| (regs), S -> smem (overlay B region, tf32)
//   mma2: O(128x64) += S · Vt^T
// Final: out = O / asum.
#define AT_PITCH 132
// float offsets
#define AT_A   0
#define AT_BS  (128 * AT_PITCH)                      // B tile, then S overlay
#define AT_V   (2 * 128 * AT_PITCH)
#define AT_AS  (2 * 128 * AT_PITCH + 64 * AT_PITCH)
#define AT_SMEM ((AT_AS + 128 * 8) * 4)              // 173056 bytes

__global__ __launch_bounds__(256) void attn_tc(float* __restrict__ out)
{
    extern __shared__ float sm[];
    float (*As)[AT_PITCH] = (float(*)[AT_PITCH])(sm + AT_A);
    float (*Bs)[AT_PITCH] = (float(*)[AT_PITCH])(sm + AT_BS);
    float (*Vs)[AT_PITCH] = (float(*)[AT_PITCH])(sm + AT_V);
    float (*asums)[8]     = (float(*)[8])(sm + AT_AS);

    int tid = threadIdx.x, wid = tid >> 5, lane = tid & 31;
    int warpM = wid >> 1, warpN = wid & 1;
    int g = lane >> 2, t = lane & 3;
    int nh = blockIdx.y;
    int n = nh >> 3, h = nh & 7;
    int qt = (int)gridDim.x - 1 - (int)blockIdx.x;   // heavy tiles first
    int q0 = qt * 128;

    const float* Ab = g_A  + (size_t)nh * SEQL * CATD;
    const float* Bb = g_B  + (size_t)nh * SEQL * CATD;
    const float* Vb = g_Vt + (size_t)nh * HDIM * SEQL;

    // A tile (already tf32-rounded): load once
    #pragma unroll
    for (int it = 0; it < 16; ++it) {
        int idx = it * 256 + tid;
        int r = idx >> 5, c4 = (idx & 31) * 4;
        *(float4*)&As[r][c4] = *(const float4*)(Ab + (size_t)(q0 + r) * CATD + c4);
    }

    float O[2][4][4];
    #pragma unroll
    for (int mb = 0; mb < 2; ++mb)
        #pragma unroll
        for (int nb = 0; nb < 4; ++nb)
            #pragma unroll
            for (int r = 0; r < 4; ++r) O[mb][nb][r] = 0.f;
    float asum[2][2] = {{0.f, 0.f}, {0.f, 0.f}};

    for (int kt = 0; kt <= qt; ++kt) {
        int k0 = kt * 128;
        __syncthreads();   // prior mma2 done reading Bs(S)/Vs; also orders As stores (iter 0)
        #pragma unroll
        for (int it = 0; it < 16; ++it) {
            int idx = it * 256 + tid;
            int r = idx >> 5, c4 = (idx & 31) * 4;
            *(float4*)&Bs[r][c4] = *(const float4*)(Bb + (size_t)(k0 + r) * CATD + c4);
        }
        #pragma unroll
        for (int it = 0; it < 8; ++it) {
            int idx = it * 256 + tid;
            int r = idx >> 5, c4 = (idx & 31) * 4;
            *(float4*)&Vs[r][c4] = *(const float4*)(Vb + (size_t)r * SEQL + k0 + c4);
        }
        __syncthreads();

        // mma1: S = A(128x128) . B^T
        float S[2][8][4];
        #pragma unroll
        for (int mb = 0; mb < 2; ++mb)
            #pragma unroll
            for (int nb = 0; nb < 8; ++nb)
                #pragma unroll
                for (int r = 0; r < 4; ++r) S[mb][nb][r] = 0.f;

        #pragma unroll 4
        for (int ks = 0; ks < 16; ++ks) {
            int k = ks * 8;
            uint32_t a[2][4];
            #pragma unroll
            for (int mb = 0; mb < 2; ++mb) {
                int r0 = warpM * 32 + mb * 16;
                a[mb][0] = __float_as_uint(As[r0 + g][k + t]);
                a[mb][1] = __float_as_uint(As[r0 + g + 8][k + t]);
                a[mb][2] = __float_as_uint(As[r0 + g][k + t + 4]);
                a[mb][3] = __float_as_uint(As[r0 + g + 8][k + t + 4]);
            }
            uint32_t b[8][2];
            #pragma unroll
            for (int nb = 0; nb < 8; ++nb) {
                int n0 = warpN * 64 + nb * 8;
                b[nb][0] = __float_as_uint(Bs[n0 + g][k + t]);
                b[nb][1] = __float_as_uint(Bs[n0 + g][k + t + 4]);
            }
            #pragma unroll
            for (int mb = 0; mb < 2; ++mb)
                #pragma unroll
                for (int nb = 0; nb < 8; ++nb)
                    mma8(S[mb][nb], a[mb], b[nb]);
        }
        __syncthreads();   // all warps done reading Bs before overlaying with S

        // epilogue: mask + |S| accumulation + store S (tf32) into Bs
        bool diag = (kt == qt);
        #pragma unroll
        for (int mb = 0; mb < 2; ++mb) {
            #pragma unroll
            for (int nb = 0; nb < 8; ++nb) {
                int col = warpN * 64 + nb * 8 + 2 * t;
                #pragma unroll
                for (int rh = 0; rh < 2; ++rh) {
                    int row = warpM * 32 + mb * 16 + g + rh * 8;
                    float v0 = S[mb][nb][rh * 2 + 0];
                    float v1 = S[mb][nb][rh * 2 + 1];
                    if (diag) {
                        if (col + 0 > row) v0 = 0.f;
                        if (col + 1 > row) v1 = 0.f;
                    }
                    asum[mb][rh] += fabsf(v0) + fabsf(v1);
                    float2 st;
                    st.x = __uint_as_float(f2tf(v0));
                    st.y = __uint_as_float(f2tf(v1));
                    *(float2*)&Bs[row][col] = st;
                }
            }
        }
        __syncthreads();

        // mma2: O += S(128x128) . Vt^T (N=64)
        #pragma unroll 4
        for (int ks = 0; ks < 16; ++ks) {
            int k = ks * 8;
            uint32_t a[2][4];
            #pragma unroll
            for (int mb = 0; mb < 2; ++mb) {
                int r0 = warpM * 32 + mb * 16;
                a[mb][0] = __float_as_uint(Bs[r0 + g][k + t]);
                a[mb][1] = __float_as_uint(Bs[r0 + g + 8][k + t]);
                a[mb][2] = __float_as_uint(Bs[r0 + g][k + t + 4]);
                a[mb][3] = __float_as_uint(Bs[r0 + g + 8][k + t + 4]);
            }
            uint32_t b[4][2];
            #pragma unroll
            for (int nb = 0; nb < 4; ++nb) {
                int n0 = warpN * 32 + nb * 8;
                b[nb][0] = __float_as_uint(Vs[n0 + g][k + t]);
                b[nb][1] = __float_as_uint(Vs[n0 + g][k + t + 4]);
            }
            #pragma unroll
            for (int mb = 0; mb < 2; ++mb)
                #pragma unroll
                for (int nb = 0; nb < 4; ++nb)
                    mma8(O[mb][nb], a[mb], b[nb]);
        }
    }

    __syncthreads();
    // per-row |S| sum: 8 partials per row -> reduce
    #pragma unroll
    for (int mb = 0; mb < 2; ++mb) {
        int r0 = warpM * 32 + mb * 16 + g;
        asums[r0][warpN * 4 + t]     = asum[mb][0];
        asums[r0 + 8][warpN * 4 + t] = asum[mb][1];
    }
    __syncthreads();
    if (tid < 128) {
        float s = 0.f;
        #pragma unroll
        for (int j = 0; j < 8; ++j) s += asums[tid][j];
        asums[tid][0] = 1.f / s;
    }
    __syncthreads();

    #pragma unroll
    for (int mb = 0; mb < 2; ++mb) {
        #pragma unroll
        for (int rh = 0; rh < 2; ++rh) {
            int row = warpM * 32 + mb * 16 + g + rh * 8;
            float inv = asums[row][0];
            int l = q0 + row;
            float* op = out + ((size_t)(n * SEQL + l)) * DMODEL + h * HDIM;
            #pragma unroll
            for (int nb = 0; nb < 4; ++nb) {
                int col = warpN * 32 + nb * 8 + 2 * t;
                float2 st;
                st.x = O[mb][nb][rh * 2 + 0] * inv;
                st.y = O[mb][nb][rh * 2 + 1] * inv;
                *(float2*)(op + col) = st;
            }
        }
    }
}

// ─────────────────────────── launch ─────────────────────────────────────────
extern "C" void kernel_launch(void* const* d_in, const int* in_sizes, int n_in,
                              void* d_out, int out_size)
{
    const float* query = (const float*)d_in[0];
    const float* key   = (const float*)d_in[1];
    const float* Wq    = (const float*)d_in[2];
    const float* Wk    = (const float*)d_in[3];
    const float* Wv    = (const float*)d_in[4];
    const float* coeff = (const float*)d_in[5];
    const float* pw    = (const float*)d_in[6];
    const float* pb    = (const float*)d_in[7];
    float* out = (float*)d_out;

    cudaFuncSetAttribute(proj_tc, cudaFuncAttributeMaxDynamicSharedMemorySize, PJ_SMEM);
    cudaFuncSetAttribute(attn_tc, cudaFuncAttributeMaxDynamicSharedMemorySize, AT_SMEM);

    proj_tc<<<dim3(32, 4, 3), 256, PJ_SMEM>>>(query, key, Wq, Wk, Wv, coeff, pw, pb);
    attn_tc<<<dim3(16, 16), 256, AT_SMEM>>>(out);
}